// round 1
// baseline (speedup 1.0000x reference)
#include <cuda_runtime.h>
#include <cstdint>
#include <cstdio>

#define M_B 4096
#define N_H 16384
#define K_D 1024
#define KSEL 32
#define CAND_MAX 8192

// ---------------- scratch (device globals; no allocation) ----------------
__device__ float g_Wt[(size_t)N_H * K_D];   // W_dec transposed: [h][d], 64MB
__device__ int   g_topk_idx[M_B * KSEL];
__device__ float g_topk_val[M_B * KSEL];

// ======================================================================
// Encoder GEMM: C[m,n] = sum_k x[m,k]*W_enc[n,k] + b_enc[n]
// fp32 via packed fma.rn.f32x2 (2x FFMA rate on sm_103a).
// Tile 128x128x8, 256 threads, 8x8 per thread (pairs along N).
// ======================================================================
__global__ __launch_bounds__(256, 2) void enc_gemm_kernel(
    const float* __restrict__ A, const float* __restrict__ B,
    const float* __restrict__ bias, float* __restrict__ C)
{
    __shared__ float As[2][8][128];
    __shared__ float Bs[2][8][128];
    const int tid = threadIdx.x;
    const int bm = blockIdx.y * 128;
    const int bn = blockIdx.x * 128;

    const int lr = tid >> 1;           // 0..127 tile row
    const int lc = (tid & 1) * 4;      // k offset 0 or 4
    const float* Ap = A + (size_t)(bm + lr) * K_D + lc;
    const float* Bp = B + (size_t)(bn + lr) * K_D + lc;

    float4 na = *(const float4*)Ap;
    float4 nb = *(const float4*)Bp;
    As[0][lc + 0][lr] = na.x; As[0][lc + 1][lr] = na.y;
    As[0][lc + 2][lr] = na.z; As[0][lc + 3][lr] = na.w;
    Bs[0][lc + 0][lr] = nb.x; Bs[0][lc + 1][lr] = nb.y;
    Bs[0][lc + 2][lr] = nb.z; Bs[0][lc + 3][lr] = nb.w;
    __syncthreads();

    const int tx = tid & 15;
    const int ty = tid >> 4;
    const int m0 = ty * 8;
    const int n0 = tx * 8;

    unsigned long long acc[8][4];
#pragma unroll
    for (int i = 0; i < 8; i++)
#pragma unroll
        for (int j = 0; j < 4; j++) acc[i][j] = 0ull;

    int buf = 0;
    for (int kt = 0; kt < K_D / 8; ++kt) {
        const bool has_next = (kt + 1 < K_D / 8);
        if (has_next) {
            na = *(const float4*)(Ap + (kt + 1) * 8);
            nb = *(const float4*)(Bp + (kt + 1) * 8);
        }
#pragma unroll
        for (int k = 0; k < 8; ++k) {
            const uint4 av0 = *(const uint4*)&As[buf][k][m0];
            const uint4 av1 = *(const uint4*)&As[buf][k][m0 + 4];
            const unsigned long long* b64 =
                (const unsigned long long*)&Bs[buf][k][n0];
            unsigned long long bp0 = b64[0], bp1 = b64[1],
                               bp2 = b64[2], bp3 = b64[3];
            unsigned int au[8] = {av0.x, av0.y, av0.z, av0.w,
                                  av1.x, av1.y, av1.z, av1.w};
#pragma unroll
            for (int i = 0; i < 8; i++) {
                unsigned long long ap;
                asm("mov.b64 %0, {%1, %1};" : "=l"(ap) : "r"(au[i]));
                asm("fma.rn.f32x2 %0, %1, %2, %0;" : "+l"(acc[i][0]) : "l"(ap), "l"(bp0));
                asm("fma.rn.f32x2 %0, %1, %2, %0;" : "+l"(acc[i][1]) : "l"(ap), "l"(bp1));
                asm("fma.rn.f32x2 %0, %1, %2, %0;" : "+l"(acc[i][2]) : "l"(ap), "l"(bp2));
                asm("fma.rn.f32x2 %0, %1, %2, %0;" : "+l"(acc[i][3]) : "l"(ap), "l"(bp3));
            }
        }
        if (has_next) {
            const int nbuf = buf ^ 1;
            As[nbuf][lc + 0][lr] = na.x; As[nbuf][lc + 1][lr] = na.y;
            As[nbuf][lc + 2][lr] = na.z; As[nbuf][lc + 3][lr] = na.w;
            Bs[nbuf][lc + 0][lr] = nb.x; Bs[nbuf][lc + 1][lr] = nb.y;
            Bs[nbuf][lc + 2][lr] = nb.z; Bs[nbuf][lc + 3][lr] = nb.w;
            __syncthreads();
            buf = nbuf;
        }
    }

    const float4 bb0 = *(const float4*)(bias + bn + n0);
    const float4 bb1 = *(const float4*)(bias + bn + n0 + 4);
#pragma unroll
    for (int i = 0; i < 8; i++) {
        float o[8];
#pragma unroll
        for (int j = 0; j < 4; j++) {
            float lo_, hi_;
            asm("mov.b64 {%0, %1}, %2;" : "=f"(lo_), "=f"(hi_) : "l"(acc[i][j]));
            o[2 * j] = lo_; o[2 * j + 1] = hi_;
        }
        o[0] += bb0.x; o[1] += bb0.y; o[2] += bb0.z; o[3] += bb0.w;
        o[4] += bb1.x; o[5] += bb1.y; o[6] += bb1.z; o[7] += bb1.w;
        float* cp = C + (size_t)(bm + m0 + i) * N_H + bn + n0;
        *(float4*)cp       = make_float4(o[0], o[1], o[2], o[3]);
        *(float4*)(cp + 4) = make_float4(o[4], o[5], o[6], o[7]);
    }
}

// ======================================================================
// Block reductions (256 threads)
// ======================================================================
__device__ __forceinline__ unsigned int block_reduce_sum(unsigned int v,
                                                         unsigned int* s_red) {
    const int tid = threadIdx.x;
#pragma unroll
    for (int o = 16; o; o >>= 1) v += __shfl_xor_sync(0xffffffffu, v, o);
    if ((tid & 31) == 0) s_red[tid >> 5] = v;
    __syncthreads();
    if (tid < 32) {
        unsigned int t = (tid < 8) ? s_red[tid] : 0u;
#pragma unroll
        for (int o = 4; o; o >>= 1) t += __shfl_xor_sync(0xffffffffu, t, o);
        if (tid == 0) s_red[0] = t;
    }
    __syncthreads();
    unsigned int r = s_red[0];
    __syncthreads();
    return r;
}

__device__ __forceinline__ unsigned int block_reduce_max(unsigned int v,
                                                         unsigned int* s_red) {
    const int tid = threadIdx.x;
#pragma unroll
    for (int o = 16; o; o >>= 1)
        v = max(v, __shfl_xor_sync(0xffffffffu, v, o));
    if ((tid & 31) == 0) s_red[tid >> 5] = v;
    __syncthreads();
    if (tid < 32) {
        unsigned int t = (tid < 8) ? s_red[tid] : 0u;
#pragma unroll
        for (int o = 4; o; o >>= 1)
            t = max(t, __shfl_xor_sync(0xffffffffu, t, o));
        if (tid == 0) s_red[0] = t;
    }
    __syncthreads();
    unsigned int r = s_red[0];
    __syncthreads();
    return r;
}

// ======================================================================
// Per-row top-K: exact 32nd-largest |v| via bound + candidate bisection.
// In-place masks the row; emits (idx,val) for the decoder.
// ======================================================================
__global__ __launch_bounds__(256) void topk_kernel(float* __restrict__ inout,
                                                   int* __restrict__ oidx,
                                                   float* __restrict__ oval)
{
    extern __shared__ unsigned char dyn_smem[];
    float* sv = (float*)dyn_smem;                         // 16384 floats
    unsigned int* cand = (unsigned int*)(sv + N_H);       // CAND_MAX entries
    __shared__ unsigned int s_red[8];
    __shared__ unsigned int s_cnum, s_sel, s_lo, s_hi;

    const int tid = threadIdx.x;
    const int row = blockIdx.x;
    float4* rp4 = (float4*)(inout + (size_t)row * N_H);
    float4* sv4 = (float4*)sv;

    if (tid == 0) { s_cnum = 0u; s_sel = 0u; }

    // load row -> smem, track max key of |v|
    unsigned int mk = 0u;
#pragma unroll
    for (int j = 0; j < 16; j++) {
        float4 v = rp4[tid + j * 256];
        sv4[tid + j * 256] = v;
        mk = max(mk, __float_as_uint(fabsf(v.x)));
        mk = max(mk, __float_as_uint(fabsf(v.y)));
        mk = max(mk, __float_as_uint(fabsf(v.z)));
        mk = max(mk, __float_as_uint(fabsf(v.w)));
    }
    __syncthreads();
    const unsigned int smax = block_reduce_max(mk, s_red);

    // find a lower bound with count(key >= bound) >= KSEL (no atomics)
    unsigned int bound = 0u;
    unsigned int esub = 1u << 23;   // one power of two in key space
    for (int tries = 0; tries < 32; ++tries) {
        bound = (smax > esub) ? (smax - esub) : 0u;
        unsigned int c = 0;
#pragma unroll
        for (int j = 0; j < 16; j++) {
            float4 v = sv4[tid + j * 256];
            c += (__float_as_uint(fabsf(v.x)) >= bound);
            c += (__float_as_uint(fabsf(v.y)) >= bound);
            c += (__float_as_uint(fabsf(v.z)) >= bound);
            c += (__float_as_uint(fabsf(v.w)) >= bound);
        }
        unsigned int tot = block_reduce_sum(c, s_red);
        if (tot >= (unsigned)KSEL || bound == 0u) break;
        esub <<= 1;
    }

    // compact candidate element indices
#pragma unroll
    for (int j = 0; j < 16; j++) {
        const int i4 = tid + j * 256;
        float4 v = sv4[i4];
        if (__float_as_uint(fabsf(v.x)) >= bound) {
            unsigned p = atomicAdd(&s_cnum, 1u);
            if (p < CAND_MAX) cand[p] = 4 * i4 + 0;
        }
        if (__float_as_uint(fabsf(v.y)) >= bound) {
            unsigned p = atomicAdd(&s_cnum, 1u);
            if (p < CAND_MAX) cand[p] = 4 * i4 + 1;
        }
        if (__float_as_uint(fabsf(v.z)) >= bound) {
            unsigned p = atomicAdd(&s_cnum, 1u);
            if (p < CAND_MAX) cand[p] = 4 * i4 + 2;
        }
        if (__float_as_uint(fabsf(v.w)) >= bound) {
            unsigned p = atomicAdd(&s_cnum, 1u);
            if (p < CAND_MAX) cand[p] = 4 * i4 + 3;
        }
    }
    __syncthreads();
    const unsigned int cnum = min(s_cnum, (unsigned)CAND_MAX);

    // bisection on uint key: T = exact KSEL-th largest key
    if (tid == 0) { s_lo = bound; s_hi = smax; }
    __syncthreads();
    for (int it = 0; it < 40; ++it) {
        const unsigned int lo = s_lo, hi = s_hi;
        if (lo >= hi) break;
        const unsigned int mid = lo + ((hi - lo + 1) >> 1);
        unsigned int c = 0;
        for (unsigned int i = tid; i < cnum; i += 256) {
            float vv = sv[cand[i]];
            c += (__float_as_uint(fabsf(vv)) >= mid);
        }
        const unsigned int t2 = block_reduce_sum(c, s_red);
        if (tid == 0) { if (t2 >= (unsigned)KSEL) s_lo = mid; else s_hi = mid - 1; }
        __syncthreads();
    }
    const unsigned int T = s_lo;

    if (tid < KSEL) { oidx[row * KSEL + tid] = 0; oval[row * KSEL + tid] = 0.f; }
    __syncthreads();

    // masked write + (idx,val) emission
#pragma unroll
    for (int j = 0; j < 16; j++) {
        const int i4 = tid + j * 256;
        float4 v = sv4[i4];
        float4 o;
        {
            bool s = __float_as_uint(fabsf(v.x)) >= T;
            o.x = s ? v.x : 0.f;
            if (s) { unsigned p = atomicAdd(&s_sel, 1u);
                     if (p < (unsigned)KSEL) { oidx[row * KSEL + p] = 4 * i4 + 0; oval[row * KSEL + p] = v.x; } }
        }
        {
            bool s = __float_as_uint(fabsf(v.y)) >= T;
            o.y = s ? v.y : 0.f;
            if (s) { unsigned p = atomicAdd(&s_sel, 1u);
                     if (p < (unsigned)KSEL) { oidx[row * KSEL + p] = 4 * i4 + 1; oval[row * KSEL + p] = v.y; } }
        }
        {
            bool s = __float_as_uint(fabsf(v.z)) >= T;
            o.z = s ? v.z : 0.f;
            if (s) { unsigned p = atomicAdd(&s_sel, 1u);
                     if (p < (unsigned)KSEL) { oidx[row * KSEL + p] = 4 * i4 + 2; oval[row * KSEL + p] = v.z; } }
        }
        {
            bool s = __float_as_uint(fabsf(v.w)) >= T;
            o.w = s ? v.w : 0.f;
            if (s) { unsigned p = atomicAdd(&s_sel, 1u);
                     if (p < (unsigned)KSEL) { oidx[row * KSEL + p] = 4 * i4 + 3; oval[row * KSEL + p] = v.w; } }
        }
        rp4[i4] = o;
    }
}

// ======================================================================
// Transpose W_dec [1024, 16384] -> g_Wt [16384, 1024]
// ======================================================================
__global__ void transpose_kernel(const float* __restrict__ W)
{
    __shared__ float t[32][33];
    const int h0 = blockIdx.x * 32;
    const int d0 = blockIdx.y * 32;
    const int tx = threadIdx.x, ty = threadIdx.y;   // 32 x 8
#pragma unroll
    for (int i = 0; i < 32; i += 8)
        t[ty + i][tx] = W[(size_t)(d0 + ty + i) * N_H + h0 + tx];
    __syncthreads();
#pragma unroll
    for (int i = 0; i < 32; i += 8)
        g_Wt[(size_t)(h0 + ty + i) * K_D + d0 + tx] = t[tx][ty + i];
}

// ======================================================================
// Decode: decoded[b,:] = sum_j val_j * Wt[idx_j,:] + b_dec
// ======================================================================
__global__ __launch_bounds__(256) void decode_kernel(const float* __restrict__ bdec,
                                                     float* __restrict__ out)
{
    __shared__ int   sidx[KSEL];
    __shared__ float sval[KSEL];
    const int row = blockIdx.x;
    const int tid = threadIdx.x;
    if (tid < KSEL) {
        sidx[tid] = g_topk_idx[row * KSEL + tid];
        sval[tid] = g_topk_val[row * KSEL + tid];
    }
    __syncthreads();

    const float4* Wt4 = (const float4*)g_Wt;
    float4 acc = make_float4(0.f, 0.f, 0.f, 0.f);
#pragma unroll 8
    for (int j = 0; j < KSEL; j++) {
        const float4 w = Wt4[(size_t)sidx[j] * (K_D / 4) + tid];
        const float s = sval[j];
        acc.x += s * w.x; acc.y += s * w.y; acc.z += s * w.z; acc.w += s * w.w;
    }
    const float4 b = ((const float4*)bdec)[tid];
    acc.x += b.x; acc.y += b.y; acc.z += b.z; acc.w += b.w;
    ((float4*)out)[(size_t)row * (K_D / 4) + tid] = acc;
}

// ======================================================================
extern "C" void kernel_launch(void* const* d_in, const int* in_sizes, int n_in,
                              void* d_out, int out_size)
{
    const float* x     = (const float*)d_in[0];
    const float* W_enc = (const float*)d_in[1];
    const float* b_enc = (const float*)d_in[2];
    const float* W_dec = (const float*)d_in[3];
    const float* b_dec = (const float*)d_in[4];

    float* out = (float*)d_out;
    float* sparse  = out;
    float* decoded = out + (size_t)M_B * N_H;

    int* d_idx = nullptr;
    float* d_val = nullptr;
    cudaGetSymbolAddress((void**)&d_idx, g_topk_idx);
    cudaGetSymbolAddress((void**)&d_val, g_topk_val);

    // 1) transpose decoder weights (L2-friendly gather layout)
    transpose_kernel<<<dim3(N_H / 32, K_D / 32), dim3(32, 8)>>>(W_dec);

    // 2) encoder GEMM (fp32, f32x2) -> writes enc into sparse region
    enc_gemm_kernel<<<dim3(N_H / 128, M_B / 128), 256>>>(x, W_enc, b_enc, sparse);

    // 3) per-row exact top-32 mask (in place) + compact (idx,val)
    const size_t tk_smem = (size_t)N_H * 4 + (size_t)CAND_MAX * 4;  // 96 KB
    cudaFuncSetAttribute(topk_kernel, cudaFuncAttributeMaxDynamicSharedMemorySize,
                         (int)tk_smem);
    topk_kernel<<<M_B, 256, tk_smem>>>(sparse, d_idx, d_val);

    // 4) sparse decode
    decode_kernel<<<M_B, 256>>>(b_dec, decoded);
}

// round 3
// speedup vs baseline: 4.7064x; 4.7064x over previous
#include <cuda_runtime.h>
#include <cuda_bf16.h>
#include <cstdint>

#define M_B 4096
#define N_H 16384
#define K_D 1024
#define KSEL 32
#define CANDCAP 512        // per-row candidate capacity (expected ~50)
#define CAND_SMEM 4096     // compaction buffer in topk_cand
#define TKC_T 512

// ---------------- scratch (device globals; no allocation) ----------------
__device__ __nv_bfloat16 g_xb[(size_t)M_B * K_D];    // 8MB   x in bf16
__device__ __nv_bfloat16 g_wb[(size_t)N_H * K_D];    // 33MB  W_enc in bf16
__device__ __nv_bfloat16 g_encbf[(size_t)M_B * N_H]; // 134MB approx enc (bf16)
__device__ float g_Wt[(size_t)N_H * K_D];            // 64MB  W_dec^T
__device__ int   g_cand[(size_t)M_B * CANDCAP];      // 8MB
__device__ int   g_ccnt[M_B];
__device__ int   g_topk_idx[M_B * KSEL];
__device__ float g_topk_val[M_B * KSEL];

// ======================= helpers =======================
__device__ __forceinline__ uint32_t smem_u32(const void* p) {
    uint32_t a;
    asm("{ .reg .u64 t; cvta.to.shared.u64 t, %1; cvt.u32.u64 %0, t; }" : "=r"(a) : "l"(p));
    return a;
}
__device__ __forceinline__ void cp16(uint32_t dst, const void* src) {
    asm volatile("cp.async.cg.shared.global [%0], [%1], 16;" :: "r"(dst), "l"(src) : "memory");
}
__device__ __forceinline__ void cp_commit() {
    asm volatile("cp.async.commit_group;" ::: "memory");
}
template <int N> __device__ __forceinline__ void cp_wait() {
    asm volatile("cp.async.wait_group %0;" :: "n"(N) : "memory");
}
__device__ __forceinline__ void ldsm4(uint32_t& r0, uint32_t& r1, uint32_t& r2,
                                      uint32_t& r3, uint32_t a) {
    asm volatile("ldmatrix.sync.aligned.m8n8.x4.shared.b16 {%0,%1,%2,%3}, [%4];"
                 : "=r"(r0), "=r"(r1), "=r"(r2), "=r"(r3) : "r"(a));
}
__device__ __forceinline__ void mma16816(float* d, uint32_t a0, uint32_t a1,
                                         uint32_t a2, uint32_t a3,
                                         uint32_t b0, uint32_t b1) {
    asm volatile("mma.sync.aligned.m16n8k16.row.col.f32.bf16.bf16.f32 "
                 "{%0,%1,%2,%3}, {%4,%5,%6,%7}, {%8,%9}, {%0,%1,%2,%3};"
                 : "+f"(d[0]), "+f"(d[1]), "+f"(d[2]), "+f"(d[3])
                 : "r"(a0), "r"(a1), "r"(a2), "r"(a3), "r"(b0), "r"(b1));
}
#define SWZ(off) ((off) ^ (((off) >> 3) & 0x70))

// block reductions, NT threads
template <int NT>
__device__ __forceinline__ unsigned brsum(unsigned v, unsigned* s_red) {
    const int tid = threadIdx.x;
#pragma unroll
    for (int o = 16; o; o >>= 1) v += __shfl_xor_sync(0xffffffffu, v, o);
    if ((tid & 31) == 0) s_red[tid >> 5] = v;
    __syncthreads();
    if (tid < 32) {
        unsigned t = (tid < NT / 32) ? s_red[tid] : 0u;
#pragma unroll
        for (int o = 16; o; o >>= 1) t += __shfl_xor_sync(0xffffffffu, t, o);
        if (tid == 0) s_red[0] = t;
    }
    __syncthreads();
    unsigned r = s_red[0];
    __syncthreads();
    return r;
}
template <int NT>
__device__ __forceinline__ unsigned brmax(unsigned v, unsigned* s_red) {
    const int tid = threadIdx.x;
#pragma unroll
    for (int o = 16; o; o >>= 1) v = max(v, __shfl_xor_sync(0xffffffffu, v, o));
    if ((tid & 31) == 0) s_red[tid >> 5] = v;
    __syncthreads();
    if (tid < 32) {
        unsigned t = (tid < NT / 32) ? s_red[tid] : 0u;
#pragma unroll
        for (int o = 16; o; o >>= 1) t = max(t, __shfl_xor_sync(0xffffffffu, t, o));
        if (tid == 0) s_red[0] = t;
    }
    __syncthreads();
    unsigned r = s_red[0];
    __syncthreads();
    return r;
}

// ======================================================================
// fp32 -> bf16 conversion kernels
// ======================================================================
__global__ __launch_bounds__(256) void convert_kernel(const float* __restrict__ src,
                                                      __nv_bfloat16* __restrict__ dst) {
    const size_t g = (size_t)blockIdx.x * 256 + threadIdx.x;
    const float4 v = ((const float4*)src)[g];
    __nv_bfloat162 lo = __floats2bfloat162_rn(v.x, v.y);
    __nv_bfloat162 hi = __floats2bfloat162_rn(v.z, v.w);
    uint32_t a, b;
    a = *(uint32_t*)&lo; b = *(uint32_t*)&hi;
    ((uint2*)dst)[g] = make_uint2(a, b);
}

// ======================================================================
// Approx encoder GEMM (bf16 HMMA): C = x @ W^T + b, output bf16.
// CTA tile 128x128, K-tiles of 64, double-buffered cp.async.
// 8 warps as 2(m) x 4(n), warp tile 64x32.
// ======================================================================
__global__ __launch_bounds__(256) void enc_hmma_kernel(const float* __restrict__ bias,
                                                       __nv_bfloat16* __restrict__ C) {
    extern __shared__ __align__(1024) char smem[];   // 2 stages x (A 16KB + B 16KB)
    const int tid = threadIdx.x;
    const int wid = tid >> 5, lane = tid & 31;
    const int bm = blockIdx.y * 128, bn = blockIdx.x * 128;
    const int wm = (wid >> 2) * 64, wn = (wid & 3) * 32;

    float acc[4][4][4];
#pragma unroll
    for (int i = 0; i < 4; i++)
#pragma unroll
        for (int j = 0; j < 4; j++)
#pragma unroll
            for (int q = 0; q < 4; q++) acc[i][j][q] = 0.f;

    const __nv_bfloat16* Abase = g_xb + (size_t)bm * K_D;
    const __nv_bfloat16* Bbase = g_wb + (size_t)bn * K_D;

    // tile loader: stage s, k-tile kt
    auto base_of = [&](int s) { return smem_u32(smem) + s * 32768; };

#define LOAD_TILE(s, kt)                                                        \
    {                                                                           \
        const uint32_t sa = base_of(s);                                         \
        const __nv_bfloat16* Ag = Abase + (kt) * 64;                            \
        const __nv_bfloat16* Bg = Bbase + (kt) * 64;                            \
        _Pragma("unroll")                                                       \
        for (int i = 0; i < 4; i++) {                                           \
            int u = tid + i * 256, row = u >> 3, kb = u & 7;                    \
            cp16(sa + SWZ(row * 128 + kb * 16), Ag + (size_t)row * K_D + kb * 8); \
        }                                                                       \
        _Pragma("unroll")                                                       \
        for (int i = 0; i < 4; i++) {                                           \
            int u = tid + i * 256, row = u >> 3, kb = u & 7;                    \
            cp16(sa + 16384 + SWZ(row * 128 + kb * 16), Bg + (size_t)row * K_D + kb * 8); \
        }                                                                       \
        cp_commit();                                                            \
    }

    LOAD_TILE(0, 0);
    int buf = 0;
    for (int kt = 0; kt < K_D / 64; ++kt) {
        if (kt + 1 < K_D / 64) { LOAD_TILE(buf ^ 1, kt + 1); cp_wait<1>(); }
        else cp_wait<0>();
        __syncthreads();

        const uint32_t sa = base_of(buf);
        const uint32_t sb = sa + 16384;
#pragma unroll
        for (int ks = 0; ks < 4; ks++) {
            uint32_t ra[4][4], rb[2][4];
#pragma unroll
            for (int mi = 0; mi < 4; mi++) {
                const int row = wm + mi * 16 + (lane & 15);
                const int koff = ks * 32 + ((lane >> 4) << 4);
                ldsm4(ra[mi][0], ra[mi][1], ra[mi][2], ra[mi][3],
                      sa + SWZ(row * 128 + koff));
            }
#pragma unroll
            for (int nb = 0; nb < 2; nb++) {
                const int nrow = wn + nb * 16 + ((lane >> 4) << 3) + (lane & 7);
                const int koff = ks * 32 + (((lane >> 3) & 1) << 4);
                ldsm4(rb[nb][0], rb[nb][1], rb[nb][2], rb[nb][3],
                      sb + SWZ(nrow * 128 + koff));
            }
#pragma unroll
            for (int mi = 0; mi < 4; mi++)
#pragma unroll
                for (int nj = 0; nj < 4; nj++)
                    mma16816(acc[mi][nj], ra[mi][0], ra[mi][1], ra[mi][2], ra[mi][3],
                             rb[nj >> 1][(nj & 1) * 2], rb[nj >> 1][(nj & 1) * 2 + 1]);
        }
        __syncthreads();
        buf ^= 1;
    }

    // epilogue: + bias, -> bf16
    const int g = lane >> 2, t = lane & 3;
#pragma unroll
    for (int mi = 0; mi < 4; mi++) {
        const int r0 = bm + wm + mi * 16 + g;
#pragma unroll
        for (int nj = 0; nj < 4; nj++) {
            const int col = bn + wn + nj * 8 + 2 * t;
            const float2 bv = *(const float2*)(bias + col);
            __nv_bfloat162 p0 = __floats2bfloat162_rn(acc[mi][nj][0] + bv.x,
                                                      acc[mi][nj][1] + bv.y);
            __nv_bfloat162 p1 = __floats2bfloat162_rn(acc[mi][nj][2] + bv.x,
                                                      acc[mi][nj][3] + bv.y);
            *(__nv_bfloat162*)(C + (size_t)r0 * N_H + col) = p0;
            *(__nv_bfloat162*)(C + (size_t)(r0 + 8) * N_H + col) = p1;
        }
    }
}

// ======================================================================
// Zero the sparse output region
// ======================================================================
__global__ __launch_bounds__(256) void zero_kernel(float4* __restrict__ p, size_t n4) {
    const size_t stride = (size_t)gridDim.x * 256;
    const float4 z = make_float4(0.f, 0.f, 0.f, 0.f);
    for (size_t i = (size_t)blockIdx.x * 256 + threadIdx.x; i < n4; i += stride)
        p[i] = z;
}

// ======================================================================
// Candidate selection on approx enc (bf16): exact 32nd largest |approx|
// key, then emit all idx with |v| >= T - delta.
// ======================================================================
__global__ __launch_bounds__(TKC_T) void topk_cand_kernel() {
    extern __shared__ unsigned char dyn[];
    uint32_t* sv = (uint32_t*)dyn;                 // 8192 words = 16384 bf16
    uint32_t* cand = (uint32_t*)(sv + 8192);       // CAND_SMEM packed key<<16|idx
    __shared__ unsigned s_red[16];
    __shared__ unsigned s_cnum, s_emit, s_lo, s_hi;

    const int tid = threadIdx.x;
    const int row = blockIdx.x;
    const uint4* rp = (const uint4*)(g_encbf + (size_t)row * N_H);

    if (tid == 0) { s_cnum = 0u; s_emit = 0u; }

    // load row (packed), track max 15-bit key
    unsigned mk = 0u;
#pragma unroll
    for (int j = 0; j < 4; j++) {
        uint4 u = rp[tid + j * TKC_T];
        const int b = (tid + j * TKC_T) * 4;
        sv[b + 0] = u.x; sv[b + 1] = u.y; sv[b + 2] = u.z; sv[b + 3] = u.w;
        mk = max(mk, u.x & 0x7FFFu); mk = max(mk, (u.x >> 16) & 0x7FFFu);
        mk = max(mk, u.y & 0x7FFFu); mk = max(mk, (u.y >> 16) & 0x7FFFu);
        mk = max(mk, u.z & 0x7FFFu); mk = max(mk, (u.z >> 16) & 0x7FFFu);
        mk = max(mk, u.w & 0x7FFFu); mk = max(mk, (u.w >> 16) & 0x7FFFu);
    }
    __syncthreads();
    const unsigned smax = brmax<TKC_T>(mk, s_red);

    // lower bound with count >= KSEL (esub doubling in bf16 key space)
    unsigned bound = 0u;
    unsigned esub = 1u << 7;
    for (int tries = 0; tries < 16; ++tries) {
        bound = (smax > esub) ? (smax - esub) : 0u;
        unsigned c = 0;
        for (int j = 0; j < 16; j++) {
            const uint32_t u = sv[tid + j * TKC_T];
            c += ((u & 0x7FFFu) >= bound);
            c += (((u >> 16) & 0x7FFFu) >= bound);
        }
        const unsigned tot = brsum<TKC_T>(c, s_red);
        if (tot >= (unsigned)KSEL || bound == 0u) break;
        esub <<= 1;
    }

    // compact candidates for bisection (packed key<<16 | idx)
    for (int j = 0; j < 16; j++) {
        const int w = tid + j * TKC_T;
        const uint32_t u = sv[w];
        const unsigned klo = u & 0x7FFFu, khi = (u >> 16) & 0x7FFFu;
        if (klo >= bound) {
            unsigned p = atomicAdd(&s_cnum, 1u);
            if (p < CAND_SMEM) cand[p] = (klo << 16) | (unsigned)(2 * w);
        }
        if (khi >= bound) {
            unsigned p = atomicAdd(&s_cnum, 1u);
            if (p < CAND_SMEM) cand[p] = (khi << 16) | (unsigned)(2 * w + 1);
        }
    }
    __syncthreads();
    const unsigned cnum = min(s_cnum, (unsigned)CAND_SMEM);

    // bisect exact 32nd-largest key
    if (tid == 0) { s_lo = bound; s_hi = smax; }
    __syncthreads();
    for (int it = 0; it < 18; ++it) {
        const unsigned lo = s_lo, hi = s_hi;
        if (lo >= hi) break;
        const unsigned mid = lo + ((hi - lo + 1) >> 1);
        const unsigned key = mid << 16;
        unsigned c = 0;
        for (unsigned i = tid; i < cnum; i += TKC_T) c += (cand[i] >= key);
        const unsigned t2 = brsum<TKC_T>(c, s_red);
        if (tid == 0) { if (t2 >= (unsigned)KSEL) s_lo = mid; else s_hi = mid - 1; }
        __syncthreads();
    }
    const unsigned short tb = (unsigned short)s_lo;
    float t32f;
    { __nv_bfloat16 h = *(__nv_bfloat16*)&tb; t32f = __bfloat162float(h); }
    const float thr = t32f - (0.0625f + 0.03125f * t32f);   // safety margin

    // emit candidates with |approx| >= thr
    for (int j = 0; j < 16; j++) {
        const int w = tid + j * TKC_T;
        const uint32_t u = sv[w];
        __nv_bfloat162 h2 = *(__nv_bfloat162*)&u;
        const float flo = fabsf(__bfloat162float(h2.x));
        const float fhi = fabsf(__bfloat162float(h2.y));
        if (flo >= thr) {
            unsigned p = atomicAdd(&s_emit, 1u);
            if (p < CANDCAP) g_cand[(size_t)row * CANDCAP + p] = 2 * w;
        }
        if (fhi >= thr) {
            unsigned p = atomicAdd(&s_emit, 1u);
            if (p < CANDCAP) g_cand[(size_t)row * CANDCAP + p] = 2 * w + 1;
        }
    }
    __syncthreads();
    if (tid == 0) g_ccnt[row] = (int)min(s_emit, (unsigned)CANDCAP);
}

// ======================================================================
// Exact fp32 recompute of candidates + exact top-32 + scatter.
// One block (256 threads, 8 warps) per row; warp per candidate.
// ======================================================================
__global__ __launch_bounds__(256) void exact_kernel(const float* __restrict__ x,
                                                    const float* __restrict__ W,
                                                    const float* __restrict__ benc,
                                                    float* __restrict__ sparse) {
    __shared__ float sx[K_D];
    __shared__ float sval[CANDCAP];
    __shared__ unsigned s_red[8];
    __shared__ unsigned s_lo, s_hi, s_sel;

    const int row = blockIdx.x;
    const int tid = threadIdx.x;
    const int wid = tid >> 5, lane = tid & 31;
    const int cnum = g_ccnt[row];

    ((float4*)sx)[tid] = ((const float4*)(x + (size_t)row * K_D))[tid];
    if (tid == 0) s_sel = 0u;
    __syncthreads();

    const float4* sx4 = (const float4*)sx;
    for (int c = wid; c < cnum; c += 8) {
        const int j = g_cand[(size_t)row * CANDCAP + c];
        const float4* wr = (const float4*)(W + (size_t)j * K_D);
        float s = 0.f;
#pragma unroll
        for (int i = 0; i < 8; i++) {
            const float4 w4 = wr[lane + i * 32];
            const float4 x4 = sx4[lane + i * 32];
            s += w4.x * x4.x + w4.y * x4.y + w4.z * x4.z + w4.w * x4.w;
        }
#pragma unroll
        for (int o = 16; o; o >>= 1) s += __shfl_xor_sync(0xffffffffu, s, o);
        if (lane == 0) sval[c] = s + benc[j];
    }
    __syncthreads();

    // max key among candidates
    unsigned mk = 0u;
    for (int c = tid; c < cnum; c += 256)
        mk = max(mk, __float_as_uint(fabsf(sval[c])));
    const unsigned smax = brmax<256>(mk, s_red);

    // bisect exact 32nd-largest fp32 key among candidates
    if (tid == 0) { s_lo = 0u; s_hi = smax; }
    __syncthreads();
    for (int it = 0; it < 34; ++it) {
        const unsigned lo = s_lo, hi = s_hi;
        if (lo >= hi) break;
        const unsigned mid = lo + ((hi - lo + 1) >> 1);
        unsigned c = 0;
        for (int i = tid; i < cnum; i += 256)
            c += (__float_as_uint(fabsf(sval[i])) >= mid);
        const unsigned t2 = brsum<256>(c, s_red);
        if (tid == 0) { if (t2 >= (unsigned)KSEL) s_lo = mid; else s_hi = mid - 1; }
        __syncthreads();
    }
    const unsigned T = s_lo;

    if (tid < KSEL) { g_topk_idx[row * KSEL + tid] = 0; g_topk_val[row * KSEL + tid] = 0.f; }
    __syncthreads();

    for (int c = tid; c < cnum; c += 256) {
        const float v = sval[c];
        if (__float_as_uint(fabsf(v)) >= T) {
            unsigned p = atomicAdd(&s_sel, 1u);
            if (p < (unsigned)KSEL) {
                const int idx = g_cand[(size_t)row * CANDCAP + c];
                sparse[(size_t)row * N_H + idx] = v;
                g_topk_idx[row * KSEL + p] = idx;
                g_topk_val[row * KSEL + p] = v;
            }
        }
    }
}

// ======================================================================
// Transpose W_dec [1024, 16384] -> g_Wt [16384, 1024]
// ======================================================================
__global__ void transpose_kernel(const float* __restrict__ W) {
    __shared__ float t[32][33];
    const int h0 = blockIdx.x * 32;
    const int d0 = blockIdx.y * 32;
    const int tx = threadIdx.x, ty = threadIdx.y;
#pragma unroll
    for (int i = 0; i < 32; i += 8)
        t[ty + i][tx] = W[(size_t)(d0 + ty + i) * N_H + h0 + tx];
    __syncthreads();
#pragma unroll
    for (int i = 0; i < 32; i += 8)
        g_Wt[(size_t)(h0 + ty + i) * K_D + d0 + tx] = t[tx][ty + i];
}

// ======================================================================
// Decode: decoded[b,:] = sum_j val_j * Wt[idx_j,:] + b_dec
// ======================================================================
__global__ __launch_bounds__(256) void decode_kernel(const float* __restrict__ bdec,
                                                     float* __restrict__ out) {
    __shared__ int sidx[KSEL];
    __shared__ float sval[KSEL];
    const int row = blockIdx.x;
    const int tid = threadIdx.x;
    if (tid < KSEL) {
        sidx[tid] = g_topk_idx[row * KSEL + tid];
        sval[tid] = g_topk_val[row * KSEL + tid];
    }
    __syncthreads();

    const float4* Wt4 = (const float4*)g_Wt;
    float4 acc = make_float4(0.f, 0.f, 0.f, 0.f);
#pragma unroll 8
    for (int j = 0; j < KSEL; j++) {
        const float4 w = Wt4[(size_t)sidx[j] * (K_D / 4) + tid];
        const float s = sval[j];
        acc.x += s * w.x; acc.y += s * w.y; acc.z += s * w.z; acc.w += s * w.w;
    }
    const float4 b = ((const float4*)bdec)[tid];
    acc.x += b.x; acc.y += b.y; acc.z += b.z; acc.w += b.w;
    ((float4*)out)[(size_t)row * (K_D / 4) + tid] = acc;
}

// ======================================================================
extern "C" void kernel_launch(void* const* d_in, const int* in_sizes, int n_in,
                              void* d_out, int out_size) {
    const float* x     = (const float*)d_in[0];
    const float* W_enc = (const float*)d_in[1];
    const float* b_enc = (const float*)d_in[2];
    const float* W_dec = (const float*)d_in[3];
    const float* b_dec = (const float*)d_in[4];

    float* out = (float*)d_out;
    float* sparse  = out;
    float* decoded = out + (size_t)M_B * N_H;

    __nv_bfloat16 *xb = nullptr, *wb = nullptr, *encbf = nullptr;
    cudaGetSymbolAddress((void**)&xb, g_xb);
    cudaGetSymbolAddress((void**)&wb, g_wb);
    cudaGetSymbolAddress((void**)&encbf, g_encbf);

    // 1) bf16 conversions of x and W_enc
    convert_kernel<<<(M_B * K_D / 4) / 256, 256>>>(x, xb);
    convert_kernel<<<((size_t)N_H * K_D / 4) / 256, 256>>>(W_enc, wb);

    // 2) W_dec transpose (decode gather layout) — independent
    transpose_kernel<<<dim3(N_H / 32, K_D / 32), dim3(32, 8)>>>(W_dec);

    // 3) approx encoder GEMM (bf16 HMMA) -> g_encbf
    cudaFuncSetAttribute(enc_hmma_kernel, cudaFuncAttributeMaxDynamicSharedMemorySize, 65536);
    enc_hmma_kernel<<<dim3(N_H / 128, M_B / 128), 256, 65536>>>(b_enc, encbf);

    // 4) zero sparse output region
    zero_kernel<<<8192, 256>>>((float4*)sparse, (size_t)M_B * N_H / 4);

    // 5) candidate selection on approx values
    const int tc_smem = (8192 + CAND_SMEM) * 4;   // 49KB
    cudaFuncSetAttribute(topk_cand_kernel, cudaFuncAttributeMaxDynamicSharedMemorySize, tc_smem);
    topk_cand_kernel<<<M_B, TKC_T, tc_smem>>>();

    // 6) exact fp32 recompute + exact top-32 + scatter
    exact_kernel<<<M_B, 256>>>(x, W_enc, b_enc, sparse);

    // 7) sparse decode
    decode_kernel<<<M_B, 256>>>(b_dec, decoded);
}